// round 1
// baseline (speedup 1.0000x reference)
#include <cuda_runtime.h>
#include <math.h>

// Problem constants
#define BQ 8
#define NB 4096      // H*W = 64*64
#define CI 128
#define CS 256
#define CT 256

// ---------------- scratch (static __device__; no allocations) ----------------
__device__ __align__(16) float g_TH[BQ * NB * CI];   // theta(x): [B,N,Ci]
__device__ __align__(16) float g_PH[BQ * NB * CI];   // phi(l):   [B,N,Ci]
__device__ __align__(16) float g_G [BQ * NB * CI];   // g(x):     [B,N,Ci]
__device__ __align__(16) float g_Y [BQ * NB * CI];   // y:        [B,N,Ci]
__device__ __align__(16) float g_S [134217728];      // logits:   [B,N,N] (512 MB)
__device__ float g_M [BQ * NB];                      // per-(b,n) row max
__device__ float g_iZ[BQ * NB];                      // per-(b,n) 1/sum(exp)
__device__ __align__(16) float g_WY[BQ * CT * NB];   // W-conv out: [B,Ct,N]
__device__ float g_mean[CT];
__device__ float g_istd[CT];

// ---------------- shared-tile loaders ----------------
// Transposed load: src is row-major [rows, ld]; fill Sh[k][row_local] for
// 8 k-values (k0..k0+7) x 128 rows (row0..row0+127). 256 threads.
__device__ __forceinline__ void load_t(const float* __restrict__ src, int row0,
                                       int ld, int k0, float (*Sh)[128], int t) {
    int r  = t >> 1;
    int kq = (t & 1) * 4;
    float4 v = *(const float4*)(src + (size_t)(row0 + r) * ld + k0 + kq);
    Sh[kq + 0][r] = v.x;
    Sh[kq + 1][r] = v.y;
    Sh[kq + 2][r] = v.z;
    Sh[kq + 3][r] = v.w;
}

// Direct load: src row-major [K, ld]; fill Sh[k][c_local] for 8 k (k0..)
// x 128 contiguous columns (c0..). 256 threads, float4 per thread.
__device__ __forceinline__ void load_d(const float* __restrict__ src, int k0,
                                       int ld, int c0, float (*Sh)[128], int t) {
    int kl = t >> 5;
    int c4 = (t & 31) * 4;
    float4 v = *(const float4*)(src + (size_t)(k0 + kl) * ld + c0 + c4);
    *(float4*)&Sh[kl][c4] = v;
}

// 8x8 register-tile FMA over a BK=8 shared tile pair.
__device__ __forceinline__ void mma8x8(const float (*As)[128], const float (*Bs)[128],
                                       int ty, int tx, float acc[8][8]) {
#pragma unroll
    for (int k = 0; k < 8; k++) {
        float a[8], bq[8];
        *(float4*)(a)     = *(const float4*)(&As[k][ty * 8]);
        *(float4*)(a + 4) = *(const float4*)(&As[k][ty * 8 + 4]);
        *(float4*)(bq)     = *(const float4*)(&Bs[k][tx * 8]);
        *(float4*)(bq + 4) = *(const float4*)(&Bs[k][tx * 8 + 4]);
#pragma unroll
        for (int i = 0; i < 8; i++)
#pragma unroll
            for (int j = 0; j < 8; j++)
                acc[i][j] = fmaf(a[i], bq[j], acc[i][j]);
    }
}

__device__ __forceinline__ float warpMax(float v) {
#pragma unroll
    for (int o = 16; o; o >>= 1) v = fmaxf(v, __shfl_xor_sync(0xffffffffu, v, o));
    return v;
}
__device__ __forceinline__ float warpSum(float v) {
#pragma unroll
    for (int o = 16; o; o >>= 1) v += __shfl_xor_sync(0xffffffffu, v, o);
    return v;
}

// ---------------- K1: 1x1-conv projections ----------------
// out[b,n,o] = sum_c in[b,c,n] * w[o,c] + bias[o];  which: 0=TH, 1=G, 2=PH
__global__ __launch_bounds__(256)
void proj_kernel(const float* __restrict__ in, const float* __restrict__ w,
                 const float* __restrict__ bias, int which) {
    const int b  = blockIdx.y;
    const int n0 = blockIdx.x * 128;
    const int t  = threadIdx.x;
    const int tx = t & 15, ty = t >> 4;
    __shared__ float As[8][128];  // As[k=c][n_local]
    __shared__ float Bs[8][128];  // Bs[k=c][o]
    float acc[8][8] = {};
    const float* inb = in + (size_t)b * CS * NB;

    for (int k0 = 0; k0 < CS; k0 += 8) {
        load_d(inb, k0, NB, n0, As, t);  // in[b, c, n0+..] contiguous in n
        load_t(w, 0, CS, k0, Bs, t);     // w[o, c]: transpose to Bs[c][o]
        __syncthreads();
        mma8x8(As, Bs, ty, tx, acc);
        __syncthreads();
    }

    float* outp = (which == 0) ? g_TH : (which == 1) ? g_G : g_PH;
    float bj[8];
    *(float4*)(bj)     = *(const float4*)(&bias[tx * 8]);
    *(float4*)(bj + 4) = *(const float4*)(&bias[tx * 8 + 4]);
    float* ob = outp + ((size_t)b * NB + n0) * CI;
#pragma unroll
    for (int i = 0; i < 8; i++) {
        float4 r0 = make_float4(acc[i][0] + bj[0], acc[i][1] + bj[1],
                                acc[i][2] + bj[2], acc[i][3] + bj[3]);
        float4 r1 = make_float4(acc[i][4] + bj[4], acc[i][5] + bj[5],
                                acc[i][6] + bj[6], acc[i][7] + bj[7]);
        *(float4*)(ob + (size_t)(ty * 8 + i) * CI + tx * 8)     = r0;
        *(float4*)(ob + (size_t)(ty * 8 + i) * CI + tx * 8 + 4) = r1;
    }
}

// ---------------- K2: S[b,n,m] = sum_c TH[b,n,c] * PH[b,m,c] ----------------
__global__ __launch_bounds__(256)
void qk_kernel() {
    const int b  = blockIdx.z;
    const int n0 = blockIdx.y * 128;
    const int m0 = blockIdx.x * 128;
    const int t  = threadIdx.x;
    const int tx = t & 15, ty = t >> 4;
    __shared__ float As[8][128];  // As[k=c][n_local]
    __shared__ float Bs[8][128];  // Bs[k=c][m_local]
    float acc[8][8] = {};
    const float* THb = g_TH + (size_t)b * NB * CI;
    const float* PHb = g_PH + (size_t)b * NB * CI;

    for (int k0 = 0; k0 < CI; k0 += 8) {
        load_t(THb, n0, CI, k0, As, t);
        load_t(PHb, m0, CI, k0, Bs, t);
        __syncthreads();
        mma8x8(As, Bs, ty, tx, acc);
        __syncthreads();
    }

    float* Sb = g_S + (size_t)b * NB * NB;
#pragma unroll
    for (int i = 0; i < 8; i++) {
        size_t row = (size_t)(n0 + ty * 8 + i) * NB;
        *(float4*)(Sb + row + m0 + tx * 8)     = *(float4*)&acc[i][0];
        *(float4*)(Sb + row + m0 + tx * 8 + 4) = *(float4*)&acc[i][4];
    }
}

// ---------------- K3: per-(b,n) row max and 1/sum(exp) over m ----------------
__global__ __launch_bounds__(256)
void rowstats_kernel() {
    const int n = blockIdx.x;
    const int b = blockIdx.y;
    const int t = threadIdx.x;
    const int lane = t & 31, wrp = t >> 5;
    const float* row = g_S + ((size_t)(b * NB + n)) * NB;
    __shared__ float red[8];

    float v[16];
    float mx = -INFINITY;
#pragma unroll
    for (int i = 0; i < 16; i++) {
        v[i] = row[t + i * 256];
        mx = fmaxf(mx, v[i]);
    }
    mx = warpMax(mx);
    if (lane == 0) red[wrp] = mx;
    __syncthreads();
    if (wrp == 0) {
        float r = (lane < 8) ? red[lane] : -INFINITY;
        r = warpMax(r);
        if (lane == 0) red[0] = r;
    }
    __syncthreads();
    const float M = red[0];
    __syncthreads();

    float s = 0.f;
#pragma unroll
    for (int i = 0; i < 16; i++) s += __expf(v[i] - M);
    s = warpSum(s);
    if (lane == 0) red[wrp] = s;
    __syncthreads();
    if (wrp == 0) {
        float r = (lane < 8) ? red[lane] : 0.f;
        r = warpSum(r);
        if (lane == 0) {
            g_M [b * NB + n] = M;
            g_iZ[b * NB + n] = 1.f / r;
        }
    }
}

// ---------------- K4: Y[b,m,c] = sum_n P[n,m] * G[n,c] ----------------
// P[n,m] = exp(S[n,m] - M[n]) * iZ[n], computed on the fly during tile load.
__global__ __launch_bounds__(256)
void av_kernel() {
    const int b  = blockIdx.y;
    const int m0 = blockIdx.x * 128;
    const int t  = threadIdx.x;
    const int tx = t & 15, ty = t >> 4;
    __shared__ float As[8][128];  // As[k=n][m_local] = P
    __shared__ float Bs[8][128];  // Bs[k=n][c]
    float acc[8][8] = {};
    const float* Sb  = g_S + (size_t)b * NB * NB;
    const float* Gb  = g_G + (size_t)b * NB * CI;
    const float* Mr  = g_M  + b * NB;
    const float* iZr = g_iZ + b * NB;

    for (int n0 = 0; n0 < NB; n0 += 8) {
        {   // P tile
            int kl = t >> 5;
            int m4 = (t & 31) * 4;
            int n  = n0 + kl;
            float Mn = Mr[n];
            float z  = iZr[n];
            float4 s4 = *(const float4*)(Sb + (size_t)n * NB + m0 + m4);
            As[kl][m4 + 0] = __expf(s4.x - Mn) * z;
            As[kl][m4 + 1] = __expf(s4.y - Mn) * z;
            As[kl][m4 + 2] = __expf(s4.z - Mn) * z;
            As[kl][m4 + 3] = __expf(s4.w - Mn) * z;
        }
        load_d(Gb, n0, CI, 0, Bs, t);
        __syncthreads();
        mma8x8(As, Bs, ty, tx, acc);
        __syncthreads();
    }

    float* Yb = g_Y + (size_t)b * NB * CI;
#pragma unroll
    for (int i = 0; i < 8; i++) {
        size_t row = (size_t)(m0 + ty * 8 + i) * CI;
        *(float4*)(Yb + row + tx * 8)     = *(float4*)&acc[i][0];
        *(float4*)(Yb + row + tx * 8 + 4) = *(float4*)&acc[i][4];
    }
}

// ---------------- K5a: WY[b,ct,n] = sum_ci w_w[ct,ci] * Y[b,n,ci] + w_b[ct] ----
__global__ __launch_bounds__(256)
void wconv_kernel(const float* __restrict__ ww, const float* __restrict__ wb) {
    const int b   = blockIdx.z;
    const int ct0 = blockIdx.y * 128;
    const int n0  = blockIdx.x * 128;
    const int t   = threadIdx.x;
    const int tx  = t & 15, ty = t >> 4;
    __shared__ float As[8][128];  // As[k=ci][ct_local]
    __shared__ float Bs[8][128];  // Bs[k=ci][n_local]
    float acc[8][8] = {};
    const float* Yb = g_Y + (size_t)b * NB * CI;

    for (int k0 = 0; k0 < CI; k0 += 8) {
        load_t(ww, ct0, CI, k0, As, t);
        load_t(Yb, n0, CI, k0, Bs, t);
        __syncthreads();
        mma8x8(As, Bs, ty, tx, acc);
        __syncthreads();
    }

#pragma unroll
    for (int i = 0; i < 8; i++) {
        int   ct   = ct0 + ty * 8 + i;
        float bias = wb[ct];
        float4 r0 = make_float4(acc[i][0] + bias, acc[i][1] + bias,
                                acc[i][2] + bias, acc[i][3] + bias);
        float4 r1 = make_float4(acc[i][4] + bias, acc[i][5] + bias,
                                acc[i][6] + bias, acc[i][7] + bias);
        size_t row = ((size_t)(b * CT + ct)) * NB;
        *(float4*)(g_WY + row + n0 + tx * 8)     = r0;
        *(float4*)(g_WY + row + n0 + tx * 8 + 4) = r1;
    }
}

// ---------------- K5b: training-mode BN stats (biased var) per channel ------
__global__ __launch_bounds__(256)
void bnstats_kernel() {
    const int ct = blockIdx.x;
    const int t  = threadIdx.x;
    const int lane = t & 31, wrp = t >> 5;
    __shared__ float redS[8], redQ[8];

    float s = 0.f, q = 0.f;
    for (int b = 0; b < BQ; b++) {
        const float* p = g_WY + ((size_t)(b * CT + ct)) * NB;
        for (int i = t; i < NB; i += 256) {
            float v = p[i];
            s += v;
            q += v * v;
        }
    }
    s = warpSum(s);
    q = warpSum(q);
    if (lane == 0) { redS[wrp] = s; redQ[wrp] = q; }
    __syncthreads();
    if (wrp == 0) {
        float rs = (lane < 8) ? redS[lane] : 0.f;
        float rq = (lane < 8) ? redQ[lane] : 0.f;
        rs = warpSum(rs);
        rq = warpSum(rq);
        if (lane == 0) {
            const float invN = 1.f / (float)(BQ * NB);
            float mean = rs * invN;
            float var  = rq * invN - mean * mean;
            g_mean[ct] = mean;
            g_istd[ct] = rsqrtf(var + 1e-5f);
        }
    }
}

// ---------------- K5c: out = BN(WY)*gamma + beta + l ----------------
__global__ __launch_bounds__(256)
void finalize_kernel(const float* __restrict__ l, const float* __restrict__ gamma,
                     const float* __restrict__ beta, float* __restrict__ out) {
    const int ct = blockIdx.x;
    const int b  = blockIdx.y;
    const float sc  = g_istd[ct] * gamma[ct];
    const float off = beta[ct] - g_mean[ct] * sc;
    const size_t base = ((size_t)(b * CT + ct)) * NB;
    for (int i = threadIdx.x * 4; i < NB; i += 256 * 4) {
        float4 w  = *(const float4*)(g_WY + base + i);
        float4 lv = *(const float4*)(l + base + i);
        float4 o;
        o.x = fmaf(w.x, sc, off) + lv.x;
        o.y = fmaf(w.y, sc, off) + lv.y;
        o.z = fmaf(w.z, sc, off) + lv.z;
        o.w = fmaf(w.w, sc, off) + lv.w;
        *(float4*)(out + base + i) = o;
    }
}

// ---------------- launch ----------------
extern "C" void kernel_launch(void* const* d_in, const int* in_sizes, int n_in,
                              void* d_out, int out_size) {
    const float* x     = (const float*)d_in[0];
    const float* l     = (const float*)d_in[1];
    const float* gw    = (const float*)d_in[2];
    const float* gb    = (const float*)d_in[3];
    const float* thw   = (const float*)d_in[4];
    const float* thb   = (const float*)d_in[5];
    const float* phw   = (const float*)d_in[6];
    const float* phb   = (const float*)d_in[7];
    const float* ww    = (const float*)d_in[8];
    const float* wb    = (const float*)d_in[9];
    const float* gamma = (const float*)d_in[10];
    const float* beta  = (const float*)d_in[11];
    float* out = (float*)d_out;

    dim3 thr(256);
    proj_kernel<<<dim3(32, BQ), thr>>>(x, thw, thb, 0);   // TH
    proj_kernel<<<dim3(32, BQ), thr>>>(x, gw,  gb,  1);   // G
    proj_kernel<<<dim3(32, BQ), thr>>>(l, phw, phb, 2);   // PH
    qk_kernel<<<dim3(32, 32, BQ), thr>>>();
    rowstats_kernel<<<dim3(NB, BQ), thr>>>();
    av_kernel<<<dim3(32, BQ), thr>>>();
    wconv_kernel<<<dim3(32, 2, BQ), thr>>>(ww, wb);
    bnstats_kernel<<<dim3(CT), thr>>>();
    finalize_kernel<<<dim3(CT, BQ), thr>>>(l, gamma, beta, out);
}

// round 4
// speedup vs baseline: 1.5807x; 1.5807x over previous
#include <cuda_runtime.h>
#include <cuda_bf16.h>
#include <cstdint>
#include <math.h>

// Problem constants
#define BQ 8
#define NB 4096      // H*W
#define CI 128
#define CS 256
#define CT 256

// ---------------- scratch (static __device__; no allocations) ----------------
__device__ __align__(16) __nv_bfloat16 g_THh[(size_t)BQ * NB * CI];  // [b][n][c]
__device__ __align__(16) __nv_bfloat16 g_THl[(size_t)BQ * NB * CI];
__device__ __align__(16) __nv_bfloat16 g_PHh[(size_t)BQ * NB * CI];  // [b][m][c]
__device__ __align__(16) __nv_bfloat16 g_PHl[(size_t)BQ * NB * CI];
__device__ __align__(16) __nv_bfloat16 g_Gh [(size_t)BQ * CI * NB];  // [b][c][n]
__device__ __align__(16) __nv_bfloat16 g_Gl [(size_t)BQ * CI * NB];
__device__ __align__(16) float g_S [(size_t)BQ * NB * NB];           // 512 MB
__device__ float g_M [BQ * NB];
__device__ float g_iZ[BQ * NB];
__device__ __align__(16) float g_Yt[(size_t)BQ * CI * NB];           // Y^T [b][c][n]
__device__ __align__(16) float g_WY[(size_t)BQ * CT * NB];
__device__ float g_mean[CT];
__device__ float g_istd[CT];

// ---------------- small helpers ----------------
__device__ __forceinline__ uint32_t smem_u32(const void* p) {
    uint32_t a;
    asm("{ .reg .u64 t; cvta.to.shared.u64 t, %1; cvt.u32.u64 %0, t; }" : "=r"(a) : "l"(p));
    return a;
}
__device__ __forceinline__ uint32_t lds32(uint32_t a) {
    uint32_t v;
    asm volatile("ld.shared.b32 %0, [%1];" : "=r"(v) : "r"(a));
    return v;
}
__device__ __forceinline__ void sts128(uint32_t a, uint4 v) {
    asm volatile("st.shared.v4.b32 [%0], {%1,%2,%3,%4};"
                 :: "r"(a), "r"(v.x), "r"(v.y), "r"(v.z), "r"(v.w));
}
__device__ __forceinline__ void sts64(uint32_t a, uint64_t v) {
    asm volatile("st.shared.b64 [%0], %1;" :: "r"(a), "l"(v));
}
__device__ __forceinline__ uint16_t f2bf(float v) {
    uint16_t r;
    asm("cvt.rn.bf16.f32 %0, %1;" : "=h"(r) : "f"(v));
    return r;
}
__device__ __forceinline__ float bf2f(uint16_t h) {
    return __uint_as_float((uint32_t)h << 16);
}

// m16n8k16 bf16 MMA, fp32 accumulate (PTX ISA standard fragment layout)
__device__ __forceinline__ void mma16816(float* d, const uint32_t* a, const uint32_t* b) {
    asm volatile(
        "mma.sync.aligned.m16n8k16.row.col.f32.bf16.bf16.f32 "
        "{%0,%1,%2,%3}, {%4,%5,%6,%7}, {%8,%9}, {%0,%1,%2,%3};"
        : "+f"(d[0]), "+f"(d[1]), "+f"(d[2]), "+f"(d[3])
        : "r"(a[0]), "r"(a[1]), "r"(a[2]), "r"(a[3]), "r"(b[0]), "r"(b[1]));
}

__device__ __forceinline__ float warpMax(float v) {
#pragma unroll
    for (int o = 16; o; o >>= 1) v = fmaxf(v, __shfl_xor_sync(0xffffffffu, v, o));
    return v;
}
__device__ __forceinline__ float warpSum(float v) {
#pragma unroll
    for (int o = 16; o; o >>= 1) v += __shfl_xor_sync(0xffffffffu, v, o);
    return v;
}

// ---------------- legacy fp32 tile helpers (proj / wconv) ----------------
__device__ __forceinline__ void load_t(const float* __restrict__ src, int row0,
                                       int ld, int k0, float (*Sh)[128], int t) {
    int r  = t >> 1;
    int kq = (t & 1) * 4;
    float4 v = *(const float4*)(src + (size_t)(row0 + r) * ld + k0 + kq);
    Sh[kq + 0][r] = v.x;
    Sh[kq + 1][r] = v.y;
    Sh[kq + 2][r] = v.z;
    Sh[kq + 3][r] = v.w;
}
__device__ __forceinline__ void load_d(const float* __restrict__ src, int k0,
                                       int ld, int c0, float (*Sh)[128], int t) {
    int kl = t >> 5;
    int c4 = (t & 31) * 4;
    float4 v = *(const float4*)(src + (size_t)(k0 + kl) * ld + c0 + c4);
    *(float4*)&Sh[kl][c4] = v;
}
__device__ __forceinline__ void mma8x8(const float (*As)[128], const float (*Bs)[128],
                                       int ty, int tx, float acc[8][8]) {
#pragma unroll
    for (int k = 0; k < 8; k++) {
        float a[8], bq[8];
        *(float4*)(a)      = *(const float4*)(&As[k][ty * 8]);
        *(float4*)(a + 4)  = *(const float4*)(&As[k][ty * 8 + 4]);
        *(float4*)(bq)     = *(const float4*)(&Bs[k][tx * 8]);
        *(float4*)(bq + 4) = *(const float4*)(&Bs[k][tx * 8 + 4]);
#pragma unroll
        for (int i = 0; i < 8; i++)
#pragma unroll
            for (int j = 0; j < 8; j++)
                acc[i][j] = fmaf(a[i], bq[j], acc[i][j]);
    }
}

// ---------------- K1: 1x1-conv projections -> bf16 hi/lo splits ----------------
// which: 0=TH ([n][c]), 1=G (transposed, [c][n]), 2=PH ([n][c])
__global__ __launch_bounds__(256)
void proj_kernel(const float* __restrict__ in, const float* __restrict__ w,
                 const float* __restrict__ bias, int which) {
    const int b  = blockIdx.y;
    const int n0 = blockIdx.x * 128;
    const int t  = threadIdx.x;
    const int tx = t & 15, ty = t >> 4;
    __shared__ float As[8][128];
    __shared__ float Bs[8][128];
    float acc[8][8] = {};
    const float* inb = in + (size_t)b * CS * NB;

    for (int k0 = 0; k0 < CS; k0 += 8) {
        load_d(inb, k0, NB, n0, As, t);
        load_t(w, 0, CS, k0, Bs, t);
        __syncthreads();
        mma8x8(As, Bs, ty, tx, acc);
        __syncthreads();
    }

    float bj[8];
    *(float4*)(bj)     = *(const float4*)(&bias[tx * 8]);
    *(float4*)(bj + 4) = *(const float4*)(&bias[tx * 8 + 4]);

    if (which != 1) {
        __nv_bfloat16* Oh = (which == 0) ? g_THh : g_PHh;
        __nv_bfloat16* Ol = (which == 0) ? g_THl : g_PHl;
        size_t base = ((size_t)b * NB + n0) * CI;
#pragma unroll
        for (int i = 0; i < 8; i++) {
            __align__(16) uint16_t h8[8], l8[8];
#pragma unroll
            for (int j = 0; j < 8; j++) {
                float v = acc[i][j] + bj[j];
                uint16_t h = f2bf(v);
                h8[j] = h;
                l8[j] = f2bf(v - bf2f(h));
            }
            size_t off = base + (size_t)(ty * 8 + i) * CI + tx * 8;
            *(uint4*)((uint16_t*)Oh + off) = *(uint4*)h8;
            *(uint4*)((uint16_t*)Ol + off) = *(uint4*)l8;
        }
    } else {
        size_t base = (size_t)b * CI * NB;
#pragma unroll
        for (int j = 0; j < 8; j++) {
            int c = tx * 8 + j;
            __align__(16) uint16_t h8[8], l8[8];
#pragma unroll
            for (int i = 0; i < 8; i++) {
                float v = acc[i][j] + bj[j];
                uint16_t h = f2bf(v);
                h8[i] = h;
                l8[i] = f2bf(v - bf2f(h));
            }
            size_t off = base + (size_t)c * NB + n0 + ty * 8;
            *(uint4*)((uint16_t*)g_Gh + off) = *(uint4*)h8;
            *(uint4*)((uint16_t*)g_Gl + off) = *(uint4*)l8;
        }
    }
}

// ---------------- K2: HMMA QK. S[b,n,m] = TH[n,:]·PH[m,:] (hi/lo bf16) --------
// smem tiles: [128 rows][128 k] bf16, row stride 272B (16B pad) -> conflict-free
#define QK_RS 272
#define QK_TILE (128 * QK_RS)   // 34816
__global__ void __launch_bounds__(256, 1) qk_mma_kernel() {
    extern __shared__ __align__(16) char sm[];
    const uint32_t smb = smem_u32(sm);
    const int t = threadIdx.x, lane = t & 31, wid = t >> 5;
    const int g = lane >> 2, tg = lane & 3;
    const int b = blockIdx.z, n0 = blockIdx.y * 128, m0 = blockIdx.x * 128;
    const int wr = wid >> 2, wc = wid & 3;
    const uint32_t Ah = smb, Al = smb + QK_TILE, Bh = smb + 2 * QK_TILE, Bl = smb + 3 * QK_TILE;
    const size_t boff = (size_t)b * NB * CI;

    {
        const __nv_bfloat16 *thh = g_THh + boff, *thl = g_THl + boff;
        const __nv_bfloat16 *phh = g_PHh + boff, *phl = g_PHl + boff;
#pragma unroll
        for (int i = t; i < 2048; i += 256) {
            int r = i >> 4, c = i & 15;
            uint32_t d = r * QK_RS + c * 16;
            sts128(Ah + d, *(const uint4*)(thh + (size_t)(n0 + r) * CI + c * 8));
            sts128(Al + d, *(const uint4*)(thl + (size_t)(n0 + r) * CI + c * 8));
            sts128(Bh + d, *(const uint4*)(phh + (size_t)(m0 + r) * CI + c * 8));
            sts128(Bl + d, *(const uint4*)(phl + (size_t)(m0 + r) * CI + c * 8));
        }
    }
    __syncthreads();

    float acc[4][4][4] = {};
    const int ar0 = wr * 64 + g, br0 = wc * 32 + g;
#pragma unroll
    for (int s = 0; s < 8; s++) {
        const int kb = s * 32 + tg * 4;   // byte offset of k0+2tg (bf16*2B)
        uint32_t ah[4][4], al[4][4], bh[4][2], bl[4][2];
#pragma unroll
        for (int i = 0; i < 4; i++) {
            uint32_t r0 = (uint32_t)(ar0 + i * 16) * QK_RS + kb;
            ah[i][0] = lds32(Ah + r0);
            ah[i][1] = lds32(Ah + r0 + 8 * QK_RS);
            ah[i][2] = lds32(Ah + r0 + 16);
            ah[i][3] = lds32(Ah + r0 + 8 * QK_RS + 16);
            al[i][0] = lds32(Al + r0);
            al[i][1] = lds32(Al + r0 + 8 * QK_RS);
            al[i][2] = lds32(Al + r0 + 16);
            al[i][3] = lds32(Al + r0 + 8 * QK_RS + 16);
        }
#pragma unroll
        for (int j = 0; j < 4; j++) {
            uint32_t r0 = (uint32_t)(br0 + j * 8) * QK_RS + kb;
            bh[j][0] = lds32(Bh + r0);
            bh[j][1] = lds32(Bh + r0 + 16);
            bl[j][0] = lds32(Bl + r0);
            bl[j][1] = lds32(Bl + r0 + 16);
        }
#pragma unroll
        for (int i = 0; i < 4; i++)
#pragma unroll
            for (int j = 0; j < 4; j++) {
                mma16816(acc[i][j], ah[i], bh[j]);
                mma16816(acc[i][j], ah[i], bl[j]);
                mma16816(acc[i][j], al[i], bh[j]);
            }
    }

    float* Sb = g_S + (size_t)b * NB * NB;
#pragma unroll
    for (int i = 0; i < 4; i++) {
        int n = n0 + wr * 64 + i * 16 + g;
#pragma unroll
        for (int j = 0; j < 4; j++) {
            int m = m0 + wc * 32 + j * 8 + 2 * tg;
            *(float2*)(Sb + (size_t)n * NB + m)       = make_float2(acc[i][j][0], acc[i][j][1]);
            *(float2*)(Sb + (size_t)(n + 8) * NB + m) = make_float2(acc[i][j][2], acc[i][j][3]);
        }
    }
}

// ---------------- K3: per-(b,n) row max and 1/sum(exp) over m ----------------
__global__ __launch_bounds__(256)
void rowstats_kernel() {
    const int n = blockIdx.x;
    const int b = blockIdx.y;
    const int t = threadIdx.x;
    const int lane = t & 31, wrp = t >> 5;
    const float* row = g_S + ((size_t)(b * NB + n)) * NB;
    __shared__ float red[8];

    float v[16];
    float mx = -INFINITY;
#pragma unroll
    for (int i = 0; i < 16; i++) {
        v[i] = row[t + i * 256];
        mx = fmaxf(mx, v[i]);
    }
    mx = warpMax(mx);
    if (lane == 0) red[wrp] = mx;
    __syncthreads();
    if (wrp == 0) {
        float r = (lane < 8) ? red[lane] : -INFINITY;
        r = warpMax(r);
        if (lane == 0) red[0] = r;
    }
    __syncthreads();
    const float M = red[0];
    __syncthreads();

    float s = 0.f;
#pragma unroll
    for (int i = 0; i < 16; i++) s += __expf(v[i] - M);
    s = warpSum(s);
    if (lane == 0) red[wrp] = s;
    __syncthreads();
    if (wrp == 0) {
        float r = (lane < 8) ? red[lane] : 0.f;
        r = warpSum(r);
        if (lane == 0) {
            g_M [b * NB + n] = M;
            g_iZ[b * NB + n] = 1.f / r;
        }
    }
}

// ---------------- K4: HMMA AV. Yt[b,c,m] = sum_n G^T[c,n] * P[n,m] ------------
// K (=n) chunked by 64. G tile [128 c][64 n], P tile stored TRANSPOSED [128 m][64 n];
// both with 144B row stride -> conflict-free 32-bit fragment loads.
#define AV_RS 144
#define AV_TILE (128 * AV_RS)   // 18432
__global__ void __launch_bounds__(256, 1) av_mma_kernel() {
    extern __shared__ __align__(16) char sm[];
    const uint32_t smb = smem_u32(sm);
    const int t = threadIdx.x, lane = t & 31, wid = t >> 5;
    const int g = lane >> 2, tg = lane & 3;
    const int b = blockIdx.y, m0 = blockIdx.x * 128;
    const int wr = wid >> 2, wc = wid & 3;
    const uint32_t Gh = smb, Gl = smb + AV_TILE, Ph = smb + 2 * AV_TILE, Pl = smb + 3 * AV_TILE;

    const __nv_bfloat16* gh = g_Gh + (size_t)b * CI * NB;
    const __nv_bfloat16* gl = g_Gl + (size_t)b * CI * NB;
    const float* Sb  = g_S  + (size_t)b * NB * NB;
    const float* Mr  = g_M  + b * NB;
    const float* iZr = g_iZ + b * NB;

    float acc[4][4][4] = {};
    const int nq = t & 15, mo = t >> 4;   // producer: 4 n-rows x 8 m-cols per thread
    const int nl0 = nq * 4, ml0 = mo * 8;

    for (int ch = 0; ch < 64; ch++) {
        const int nb0 = ch * 64;
        __syncthreads();   // prior-iteration smem reads complete
        // G tiles
#pragma unroll
        for (int i = t; i < 1024; i += 256) {
            int r = i >> 3, c = i & 7;
            uint32_t d = r * AV_RS + c * 16;
            sts128(Gh + d, *(const uint4*)(gh + (size_t)r * NB + nb0 + c * 8));
            sts128(Gl + d, *(const uint4*)(gl + (size_t)r * NB + nb0 + c * 8));
        }
        // P tile (transposed store, packed 4 n per 64-bit write)
        {
            uint64_t hp[8] = {}, lp[8] = {};
#pragma unroll
            for (int nn = 0; nn < 4; nn++) {
                const int n = nb0 + nl0 + nn;
                const float Mn = Mr[n], z = iZr[n];
                const float* sr = Sb + (size_t)n * NB + m0 + ml0;
                float4 v0 = *(const float4*)sr;
                float4 v1 = *(const float4*)(sr + 4);
                float p[8] = {v0.x, v0.y, v0.z, v0.w, v1.x, v1.y, v1.z, v1.w};
#pragma unroll
                for (int mm = 0; mm < 8; mm++) {
                    float pv = __expf(p[mm] - Mn) * z;
                    uint16_t h = f2bf(pv);
                    uint16_t lo = f2bf(pv - bf2f(h));
                    hp[mm] |= (uint64_t)h  << (16 * nn);
                    lp[mm] |= (uint64_t)lo << (16 * nn);
                }
            }
#pragma unroll
            for (int mm = 0; mm < 8; mm++) {
                uint32_t d = (uint32_t)(ml0 + mm) * AV_RS + nl0 * 2;
                sts64(Ph + d, hp[mm]);
                sts64(Pl + d, lp[mm]);
            }
        }
        __syncthreads();

#pragma unroll
        for (int s = 0; s < 4; s++) {
            const int kb = s * 32 + tg * 4;
            uint32_t ah[4][4], al[4][4], bh[4][2], bl[4][2];
#pragma unroll
            for (int i = 0; i < 4; i++) {
                uint32_t r0 = (uint32_t)(wr * 64 + i * 16 + g) * AV_RS + kb;
                ah[i][0] = lds32(Gh + r0);
                ah[i][1] = lds32(Gh + r0 + 8 * AV_RS);
                ah[i][2] = lds32(Gh + r0 + 16);
                ah[i][3] = lds32(Gh + r0 + 8 * AV_RS + 16);
                al[i][0] = lds32(Gl + r0);
                al[i][1] = lds32(Gl + r0 + 8 * AV_RS);
                al[i][2] = lds32(Gl + r0 + 16);
                al[i][3] = lds32(Gl + r0 + 8 * AV_RS + 16);
            }
#pragma unroll
            for (int j = 0; j < 4; j++) {
                uint32_t r0 = (uint32_t)(wc * 32 + j * 8 + g) * AV_RS + kb;
                bh[j][0] = lds32(Ph + r0);
                bh[j][1] = lds32(Ph + r0 + 16);
                bl[j][0] = lds32(Pl + r0);
                bl[j][1] = lds32(Pl + r0 + 16);
            }
#pragma unroll
            for (int i = 0; i < 4; i++)
#pragma unroll
                for (int j = 0; j < 4; j++) {
                    mma16816(acc[i][j], ah[i], bh[j]);
                    mma16816(acc[i][j], ah[i], bl[j]);
                    mma16816(acc[i][j], al[i], bh[j]);
                }
        }
    }

    float* Yb = g_Yt + (size_t)b * CI * NB;
#pragma unroll
    for (int i = 0; i < 4; i++) {
        int c = wr * 64 + i * 16 + g;
#pragma unroll
        for (int j = 0; j < 4; j++) {
            int m = m0 + wc * 32 + j * 8 + 2 * tg;
            *(float2*)(Yb + (size_t)c * NB + m)       = make_float2(acc[i][j][0], acc[i][j][1]);
            *(float2*)(Yb + (size_t)(c + 8) * NB + m) = make_float2(acc[i][j][2], acc[i][j][3]);
        }
    }
}

// ---------------- K5a: WY[b,ct,n] = sum_ci w_w[ct,ci] * Yt[ci,n] + w_b[ct] ----
__global__ __launch_bounds__(256)
void wconv_kernel(const float* __restrict__ ww, const float* __restrict__ wb) {
    const int b   = blockIdx.z;
    const int ct0 = blockIdx.y * 128;
    const int n0  = blockIdx.x * 128;
    const int t   = threadIdx.x;
    const int tx  = t & 15, ty = t >> 4;
    __shared__ float As[8][128];
    __shared__ float Bs[8][128];
    float acc[8][8] = {};
    const float* Ytb = g_Yt + (size_t)b * CI * NB;

    for (int k0 = 0; k0 < CI; k0 += 8) {
        load_t(ww, ct0, CI, k0, As, t);
        load_d(Ytb, k0, NB, n0, Bs, t);
        __syncthreads();
        mma8x8(As, Bs, ty, tx, acc);
        __syncthreads();
    }

#pragma unroll
    for (int i = 0; i < 8; i++) {
        int   ct   = ct0 + ty * 8 + i;
        float bias = wb[ct];
        float4 r0 = make_float4(acc[i][0] + bias, acc[i][1] + bias,
                                acc[i][2] + bias, acc[i][3] + bias);
        float4 r1 = make_float4(acc[i][4] + bias, acc[i][5] + bias,
                                acc[i][6] + bias, acc[i][7] + bias);
        size_t row = ((size_t)(b * CT + ct)) * NB;
        *(float4*)(g_WY + row + n0 + tx * 8)     = r0;
        *(float4*)(g_WY + row + n0 + tx * 8 + 4) = r1;
    }
}

// ---------------- K5b: BN stats ----------------
__global__ __launch_bounds__(256)
void bnstats_kernel() {
    const int ct = blockIdx.x;
    const int t  = threadIdx.x;
    const int lane = t & 31, wrp = t >> 5;
    __shared__ float redS[8], redQ[8];

    float s = 0.f, q = 0.f;
    for (int b = 0; b < BQ; b++) {
        const float* p = g_WY + ((size_t)(b * CT + ct)) * NB;
        for (int i = t; i < NB; i += 256) {
            float v = p[i];
            s += v;
            q += v * v;
        }
    }
    s = warpSum(s);
    q = warpSum(q);
    if (lane == 0) { redS[wrp] = s; redQ[wrp] = q; }
    __syncthreads();
    if (wrp == 0) {
        float rs = (lane < 8) ? redS[lane] : 0.f;
        float rq = (lane < 8) ? redQ[lane] : 0.f;
        rs = warpSum(rs);
        rq = warpSum(rq);
        if (lane == 0) {
            const float invN = 1.f / (float)(BQ * NB);
            float mean = rs * invN;
            float var  = rq * invN - mean * mean;
            g_mean[ct] = mean;
            g_istd[ct] = rsqrtf(var + 1e-5f);
        }
    }
}

// ---------------- K5c: out = BN(WY)*gamma + beta + l ----------------
__global__ __launch_bounds__(256)
void finalize_kernel(const float* __restrict__ l, const float* __restrict__ gamma,
                     const float* __restrict__ beta, float* __restrict__ out) {
    const int ct = blockIdx.x;
    const int b  = blockIdx.y;
    const float sc  = g_istd[ct] * gamma[ct];
    const float off = beta[ct] - g_mean[ct] * sc;
    const size_t base = ((size_t)(b * CT + ct)) * NB;
    for (int i = threadIdx.x * 4; i < NB; i += 256 * 4) {
        float4 w  = *(const float4*)(g_WY + base + i);
        float4 lv = *(const float4*)(l + base + i);
        float4 o;
        o.x = fmaf(w.x, sc, off) + lv.x;
        o.y = fmaf(w.y, sc, off) + lv.y;
        o.z = fmaf(w.z, sc, off) + lv.z;
        o.w = fmaf(w.w, sc, off) + lv.w;
        *(float4*)(out + base + i) = o;
    }
}

// ---------------- launch ----------------
extern "C" void kernel_launch(void* const* d_in, const int* in_sizes, int n_in,
                              void* d_out, int out_size) {
    const float* x     = (const float*)d_in[0];
    const float* l     = (const float*)d_in[1];
    const float* gw    = (const float*)d_in[2];
    const float* gb    = (const float*)d_in[3];
    const float* thw   = (const float*)d_in[4];
    const float* thb   = (const float*)d_in[5];
    const float* phw   = (const float*)d_in[6];
    const float* phb   = (const float*)d_in[7];
    const float* ww    = (const float*)d_in[8];
    const float* wb    = (const float*)d_in[9];
    const float* gamma = (const float*)d_in[10];
    const float* beta  = (const float*)d_in[11];
    float* out = (float*)d_out;

    static int smem_set = 0;
    if (!smem_set) {
        cudaFuncSetAttribute(qk_mma_kernel, cudaFuncAttributeMaxDynamicSharedMemorySize, 4 * QK_TILE);
        cudaFuncSetAttribute(av_mma_kernel, cudaFuncAttributeMaxDynamicSharedMemorySize, 4 * AV_TILE);
        smem_set = 1;
    }

    dim3 thr(256);
    proj_kernel<<<dim3(32, BQ), thr>>>(x, thw, thb, 0);   // TH
    proj_kernel<<<dim3(32, BQ), thr>>>(x, gw,  gb,  1);   // G (transposed)
    proj_kernel<<<dim3(32, BQ), thr>>>(l, phw, phb, 2);   // PH
    qk_mma_kernel<<<dim3(32, 32, BQ), thr, 4 * QK_TILE>>>();
    rowstats_kernel<<<dim3(NB, BQ), thr>>>();
    av_mma_kernel<<<dim3(32, BQ), thr, 4 * AV_TILE>>>();
    wconv_kernel<<<dim3(32, 2, BQ), thr>>>(ww, wb);
    bnstats_kernel<<<dim3(CT), thr>>>();
    finalize_kernel<<<dim3(CT, BQ), thr>>>(l, gamma, beta, out);
}

// round 5
// speedup vs baseline: 1.6591x; 1.0496x over previous
#include <cuda_runtime.h>
#include <cuda_bf16.h>
#include <cstdint>
#include <math.h>

// Problem constants
#define BQ 8
#define NB 4096      // H*W
#define CI 128
#define CS 256
#define CT 256

// ---------------- scratch (static __device__; no allocations) ----------------
__device__ __align__(16) __nv_bfloat16 g_THh[(size_t)BQ * NB * CI];  // [b][n][c]
__device__ __align__(16) __nv_bfloat16 g_THl[(size_t)BQ * NB * CI];
__device__ __align__(16) __nv_bfloat16 g_PHh[(size_t)BQ * NB * CI];  // [b][m][c]
__device__ __align__(16) __nv_bfloat16 g_PHl[(size_t)BQ * NB * CI];
__device__ __align__(16) __nv_bfloat16 g_Gh [(size_t)BQ * CI * NB];  // [b][c][n]
__device__ __align__(16) __nv_bfloat16 g_Gl [(size_t)BQ * CI * NB];
__device__ __align__(16) float g_S [(size_t)BQ * NB * NB];           // 512 MB
__device__ float g_M [BQ * NB];
__device__ float g_iZ[BQ * NB];
__device__ __align__(16) float g_Yt[(size_t)BQ * CI * NB];           // Y^T [b][c][n]
__device__ __align__(16) float g_WY[(size_t)BQ * CT * NB];
__device__ float g_mean[CT];
__device__ float g_istd[CT];

// ---------------- small helpers ----------------
__device__ __forceinline__ uint32_t smem_u32(const void* p) {
    uint32_t a;
    asm("{ .reg .u64 t; cvta.to.shared.u64 t, %1; cvt.u32.u64 %0, t; }" : "=r"(a) : "l"(p));
    return a;
}
__device__ __forceinline__ void sts128(uint32_t a, uint4 v) {
    asm volatile("st.shared.v4.b32 [%0], {%1,%2,%3,%4};"
                 :: "r"(a), "r"(v.x), "r"(v.y), "r"(v.z), "r"(v.w));
}
__device__ __forceinline__ void sts64(uint32_t a, uint64_t v) {
    asm volatile("st.shared.b64 [%0], %1;" :: "r"(a), "l"(v));
}
__device__ __forceinline__ uint16_t f2bf(float v) {
    uint16_t r;
    asm("cvt.rn.bf16.f32 %0, %1;" : "=h"(r) : "f"(v));
    return r;
}
__device__ __forceinline__ float bf2f(uint16_t h) {
    return __uint_as_float((uint32_t)h << 16);
}
__device__ __forceinline__ void ldm_x4(uint32_t* r, uint32_t a) {
    asm volatile("ldmatrix.sync.aligned.m8n8.x4.shared.b16 {%0,%1,%2,%3}, [%4];"
                 : "=r"(r[0]), "=r"(r[1]), "=r"(r[2]), "=r"(r[3]) : "r"(a));
}
__device__ __forceinline__ void cp16(uint32_t saddr, const void* gaddr) {
    asm volatile("cp.async.cg.shared.global [%0], [%1], 16;" :: "r"(saddr), "l"(gaddr));
}
#define CP_COMMIT() asm volatile("cp.async.commit_group;" ::: "memory")
#define CP_WAIT0()  asm volatile("cp.async.wait_group 0;" ::: "memory")

// m16n8k16 bf16 MMA, fp32 accumulate
__device__ __forceinline__ void mma16816(float* d, const uint32_t* a, const uint32_t* b) {
    asm volatile(
        "mma.sync.aligned.m16n8k16.row.col.f32.bf16.bf16.f32 "
        "{%0,%1,%2,%3}, {%4,%5,%6,%7}, {%8,%9}, {%0,%1,%2,%3};"
        : "+f"(d[0]), "+f"(d[1]), "+f"(d[2]), "+f"(d[3])
        : "r"(a[0]), "r"(a[1]), "r"(a[2]), "r"(a[3]), "r"(b[0]), "r"(b[1]));
}

__device__ __forceinline__ float warpMax(float v) {
#pragma unroll
    for (int o = 16; o; o >>= 1) v = fmaxf(v, __shfl_xor_sync(0xffffffffu, v, o));
    return v;
}
__device__ __forceinline__ float warpSum(float v) {
#pragma unroll
    for (int o = 16; o; o >>= 1) v += __shfl_xor_sync(0xffffffffu, v, o);
    return v;
}

// ---------------- legacy fp32 tile helpers (proj / wconv) ----------------
__device__ __forceinline__ void load_t(const float* __restrict__ src, int row0,
                                       int ld, int k0, float (*Sh)[128], int t) {
    int r  = t >> 1;
    int kq = (t & 1) * 4;
    float4 v = *(const float4*)(src + (size_t)(row0 + r) * ld + k0 + kq);
    Sh[kq + 0][r] = v.x;
    Sh[kq + 1][r] = v.y;
    Sh[kq + 2][r] = v.z;
    Sh[kq + 3][r] = v.w;
}
__device__ __forceinline__ void load_d(const float* __restrict__ src, int k0,
                                       int ld, int c0, float (*Sh)[128], int t) {
    int kl = t >> 5;
    int c4 = (t & 31) * 4;
    float4 v = *(const float4*)(src + (size_t)(k0 + kl) * ld + c0 + c4);
    *(float4*)&Sh[kl][c4] = v;
}
__device__ __forceinline__ void mma8x8(const float (*As)[128], const float (*Bs)[128],
                                       int ty, int tx, float acc[8][8]) {
#pragma unroll
    for (int k = 0; k < 8; k++) {
        float a[8], bq[8];
        *(float4*)(a)      = *(const float4*)(&As[k][ty * 8]);
        *(float4*)(a + 4)  = *(const float4*)(&As[k][ty * 8 + 4]);
        *(float4*)(bq)     = *(const float4*)(&Bs[k][tx * 8]);
        *(float4*)(bq + 4) = *(const float4*)(&Bs[k][tx * 8 + 4]);
#pragma unroll
        for (int i = 0; i < 8; i++)
#pragma unroll
            for (int j = 0; j < 8; j++)
                acc[i][j] = fmaf(a[i], bq[j], acc[i][j]);
    }
}

// ---------------- K1: 1x1-conv projections -> bf16 hi/lo splits ----------------
__global__ __launch_bounds__(256)
void proj_kernel(const float* __restrict__ in, const float* __restrict__ w,
                 const float* __restrict__ bias, int which) {
    const int b  = blockIdx.y;
    const int n0 = blockIdx.x * 128;
    const int t  = threadIdx.x;
    const int tx = t & 15, ty = t >> 4;
    __shared__ float As[8][128];
    __shared__ float Bs[8][128];
    float acc[8][8] = {};
    const float* inb = in + (size_t)b * CS * NB;

    for (int k0 = 0; k0 < CS; k0 += 8) {
        load_d(inb, k0, NB, n0, As, t);
        load_t(w, 0, CS, k0, Bs, t);
        __syncthreads();
        mma8x8(As, Bs, ty, tx, acc);
        __syncthreads();
    }

    float bj[8];
    *(float4*)(bj)     = *(const float4*)(&bias[tx * 8]);
    *(float4*)(bj + 4) = *(const float4*)(&bias[tx * 8 + 4]);

    if (which != 1) {
        __nv_bfloat16* Oh = (which == 0) ? g_THh : g_PHh;
        __nv_bfloat16* Ol = (which == 0) ? g_THl : g_PHl;
        size_t base = ((size_t)b * NB + n0) * CI;
#pragma unroll
        for (int i = 0; i < 8; i++) {
            __align__(16) uint16_t h8[8], l8[8];
#pragma unroll
            for (int j = 0; j < 8; j++) {
                float v = acc[i][j] + bj[j];
                uint16_t h = f2bf(v);
                h8[j] = h;
                l8[j] = f2bf(v - bf2f(h));
            }
            size_t off = base + (size_t)(ty * 8 + i) * CI + tx * 8;
            *(uint4*)((uint16_t*)Oh + off) = *(uint4*)h8;
            *(uint4*)((uint16_t*)Ol + off) = *(uint4*)l8;
        }
    } else {
        size_t base = (size_t)b * CI * NB;
#pragma unroll
        for (int j = 0; j < 8; j++) {
            int c = tx * 8 + j;
            __align__(16) uint16_t h8[8], l8[8];
#pragma unroll
            for (int i = 0; i < 8; i++) {
                float v = acc[i][j] + bj[j];
                uint16_t h = f2bf(v);
                h8[i] = h;
                l8[i] = f2bf(v - bf2f(h));
            }
            size_t off = base + (size_t)c * NB + n0 + ty * 8;
            *(uint4*)((uint16_t*)g_Gh + off) = *(uint4*)h8;
            *(uint4*)((uint16_t*)g_Gl + off) = *(uint4*)l8;
        }
    }
}

// ---------------- K2: HMMA QK with ldmatrix ----------------
#define QK_RS 272
#define QK_TILE (128 * QK_RS)   // 34816
__global__ void __launch_bounds__(256, 1) qk_mma_kernel() {
    extern __shared__ __align__(16) char sm[];
    const uint32_t smb = smem_u32(sm);
    const int t = threadIdx.x, lane = t & 31, wid = t >> 5;
    const int g = lane >> 2, tg = lane & 3;
    const int b = blockIdx.z, n0 = blockIdx.y * 128, m0 = blockIdx.x * 128;
    const int wr = wid >> 2, wc = wid & 3;
    const uint32_t Ah = smb, Al = smb + QK_TILE, Bh = smb + 2 * QK_TILE, Bl = smb + 3 * QK_TILE;
    const size_t boff = (size_t)b * NB * CI;

    {
        const __nv_bfloat16 *thh = g_THh + boff, *thl = g_THl + boff;
        const __nv_bfloat16 *phh = g_PHh + boff, *phl = g_PHl + boff;
#pragma unroll
        for (int i = t; i < 2048; i += 256) {
            int r = i >> 4, c = i & 15;
            uint32_t d = r * QK_RS + c * 16;
            sts128(Ah + d, *(const uint4*)(thh + (size_t)(n0 + r) * CI + c * 8));
            sts128(Al + d, *(const uint4*)(thl + (size_t)(n0 + r) * CI + c * 8));
            sts128(Bh + d, *(const uint4*)(phh + (size_t)(m0 + r) * CI + c * 8));
            sts128(Bl + d, *(const uint4*)(phl + (size_t)(m0 + r) * CI + c * 8));
        }
    }
    __syncthreads();

    float acc[4][4][4] = {};
    // ldmatrix lane->address maps
    const uint32_t aOff = (uint32_t)(wr * 64 + (lane & 15)) * QK_RS + ((lane >> 4) * 16);
    const uint32_t bOff = (uint32_t)(wc * 32 + (lane & 7) + ((lane >> 4) << 3)) * QK_RS
                        + (((lane >> 3) & 1) * 16);
#pragma unroll
    for (int s = 0; s < 8; s++) {
        const uint32_t kb = s * 32;
        uint32_t ah[4][4], al[4][4], bh[2][4], bl[2][4];
#pragma unroll
        for (int i = 0; i < 4; i++) {
            ldm_x4(ah[i], Ah + aOff + i * 16 * QK_RS + kb);
            ldm_x4(al[i], Al + aOff + i * 16 * QK_RS + kb);
        }
#pragma unroll
        for (int p = 0; p < 2; p++) {
            ldm_x4(bh[p], Bh + bOff + p * 16 * QK_RS + kb);
            ldm_x4(bl[p], Bl + bOff + p * 16 * QK_RS + kb);
        }
#pragma unroll
        for (int i = 0; i < 4; i++)
#pragma unroll
            for (int j = 0; j < 4; j++) {
                const uint32_t* bhf = &bh[j >> 1][(j & 1) * 2];
                const uint32_t* blf = &bl[j >> 1][(j & 1) * 2];
                mma16816(acc[i][j], ah[i], bhf);
                mma16816(acc[i][j], ah[i], blf);
                mma16816(acc[i][j], al[i], bhf);
            }
    }

    float* Sb = g_S + (size_t)b * NB * NB;
#pragma unroll
    for (int i = 0; i < 4; i++) {
        int n = n0 + wr * 64 + i * 16 + g;
#pragma unroll
        for (int j = 0; j < 4; j++) {
            int m = m0 + wc * 32 + j * 8 + 2 * tg;
            *(float2*)(Sb + (size_t)n * NB + m)       = make_float2(acc[i][j][0], acc[i][j][1]);
            *(float2*)(Sb + (size_t)(n + 8) * NB + m) = make_float2(acc[i][j][2], acc[i][j][3]);
        }
    }
}

// ---------------- K3: per-(b,n) row max and 1/sum(exp) over m ----------------
__global__ __launch_bounds__(256)
void rowstats_kernel() {
    const int n = blockIdx.x;
    const int b = blockIdx.y;
    const int t = threadIdx.x;
    const int lane = t & 31, wrp = t >> 5;
    const float* row = g_S + ((size_t)(b * NB + n)) * NB;
    __shared__ float red[8];

    float v[16];
    float mx = -INFINITY;
#pragma unroll
    for (int i = 0; i < 16; i++) {
        v[i] = row[t + i * 256];
        mx = fmaxf(mx, v[i]);
    }
    mx = warpMax(mx);
    if (lane == 0) red[wrp] = mx;
    __syncthreads();
    if (wrp == 0) {
        float r = (lane < 8) ? red[lane] : -INFINITY;
        r = warpMax(r);
        if (lane == 0) red[0] = r;
    }
    __syncthreads();
    const float M = red[0];
    __syncthreads();

    float s = 0.f;
#pragma unroll
    for (int i = 0; i < 16; i++) s += __expf(v[i] - M);
    s = warpSum(s);
    if (lane == 0) red[wrp] = s;
    __syncthreads();
    if (wrp == 0) {
        float r = (lane < 8) ? red[lane] : 0.f;
        r = warpSum(r);
        if (lane == 0) {
            g_M [b * NB + n] = M;
            g_iZ[b * NB + n] = 1.f / r;
        }
    }
}

// ---------------- K4: HMMA AV, pipelined (cp.async G + S reg prefetch) --------
#define AV_RS 144
#define AV_TILE (128 * AV_RS)            // 18432
#define AV_BUF  (4 * AV_TILE)            // Gh,Gl,Ph,Pl per buffer = 73728
__global__ void __launch_bounds__(256, 1) av_mma_kernel() {
    extern __shared__ __align__(16) char sm[];
    const uint32_t smb = smem_u32(sm);
    const int t = threadIdx.x, lane = t & 31, wid = t >> 5;
    const int g = lane >> 2, tg = lane & 3;
    const int b = blockIdx.y, m0 = blockIdx.x * 128;
    const int wr = wid >> 2, wc = wid & 3;

    const __nv_bfloat16* gh = g_Gh + (size_t)b * CI * NB;
    const __nv_bfloat16* gl = g_Gl + (size_t)b * CI * NB;
    const float* Sb  = g_S  + (size_t)b * NB * NB;
    const float* Mr  = g_M  + b * NB;
    const float* iZr = g_iZ + b * NB;

    const int nl0 = (t & 15) * 4, ml0 = (t >> 4) * 8;   // producer mapping
    float acc[4][4][4] = {};
    float4 sv[8];
    float  Mn[4], zz[4];

    // buffer base addresses
    uint32_t GhB[2], GlB[2], PhB[2], PlB[2];
#pragma unroll
    for (int u = 0; u < 2; u++) {
        GhB[u] = smb + u * AV_BUF;
        GlB[u] = smb + u * AV_BUF + AV_TILE;
        PhB[u] = smb + u * AV_BUF + 2 * AV_TILE;
        PlB[u] = smb + u * AV_BUF + 3 * AV_TILE;
    }

    // ldmatrix lane->address maps
    const uint32_t aOff = (uint32_t)(wr * 64 + (lane & 15)) * AV_RS + ((lane >> 4) * 16);
    const uint32_t bOff = (uint32_t)(wc * 32 + (lane & 7) + ((lane >> 4) << 3)) * AV_RS
                        + (((lane >> 3) & 1) * 16);

    // --- helpers as lambdas ---
    auto cpG = [&](int ch, int u) {
        const int nb0 = ch * 64;
#pragma unroll
        for (int i = t; i < 1024; i += 256) {
            int r = i >> 3, c = i & 7;
            uint32_t d = r * AV_RS + c * 16;
            cp16(GhB[u] + d, gh + (size_t)r * NB + nb0 + c * 8);
            cp16(GlB[u] + d, gl + (size_t)r * NB + nb0 + c * 8);
        }
        CP_COMMIT();
    };
    auto ldgS = [&](int ch) {
        const int nb0 = ch * 64;
#pragma unroll
        for (int nn = 0; nn < 4; nn++) {
            int n = nb0 + nl0 + nn;
            Mn[nn] = Mr[n];
            zz[nn] = iZr[n];
            const float* sr = Sb + (size_t)n * NB + m0 + ml0;
            sv[2 * nn]     = *(const float4*)sr;
            sv[2 * nn + 1] = *(const float4*)(sr + 4);
        }
    };
    auto expStore = [&](int u) {
        uint64_t hp[8] = {}, lp[8] = {};
#pragma unroll
        for (int nn = 0; nn < 4; nn++) {
            float p[8] = {sv[2 * nn].x, sv[2 * nn].y, sv[2 * nn].z, sv[2 * nn].w,
                          sv[2 * nn + 1].x, sv[2 * nn + 1].y, sv[2 * nn + 1].z, sv[2 * nn + 1].w};
#pragma unroll
            for (int mm = 0; mm < 8; mm++) {
                float pv = __expf(p[mm] - Mn[nn]) * zz[nn];
                uint16_t h  = f2bf(pv);
                uint16_t lo = f2bf(pv - bf2f(h));
                hp[mm] |= (uint64_t)h  << (16 * nn);
                lp[mm] |= (uint64_t)lo << (16 * nn);
            }
        }
#pragma unroll
        for (int mm = 0; mm < 8; mm++) {
            uint32_t d = (uint32_t)(ml0 + mm) * AV_RS + nl0 * 2;
            sts64(PhB[u] + d, hp[mm]);
            sts64(PlB[u] + d, lp[mm]);
        }
    };
    auto mmaPhase = [&](int u) {
#pragma unroll
        for (int s = 0; s < 4; s++) {
            const uint32_t kb = s * 32;
            uint32_t ah[4][4], al[4][4], bh[2][4], bl[2][4];
#pragma unroll
            for (int i = 0; i < 4; i++) {
                ldm_x4(ah[i], GhB[u] + aOff + i * 16 * AV_RS + kb);
                ldm_x4(al[i], GlB[u] + aOff + i * 16 * AV_RS + kb);
            }
#pragma unroll
            for (int p = 0; p < 2; p++) {
                ldm_x4(bh[p], PhB[u] + bOff + p * 16 * AV_RS + kb);
                ldm_x4(bl[p], PlB[u] + bOff + p * 16 * AV_RS + kb);
            }
#pragma unroll
            for (int i = 0; i < 4; i++)
#pragma unroll
                for (int j = 0; j < 4; j++) {
                    const uint32_t* bhf = &bh[j >> 1][(j & 1) * 2];
                    const uint32_t* blf = &bl[j >> 1][(j & 1) * 2];
                    mma16816(acc[i][j], ah[i], bhf);
                    mma16816(acc[i][j], ah[i], blf);
                    mma16816(acc[i][j], al[i], bhf);
                }
        }
    };

    // --- prologue: chunk 0 ---
    cpG(0, 0);
    ldgS(0);
    expStore(0);
    CP_WAIT0();
    __syncthreads();

    for (int ch = 0; ch < 64; ch++) {
        const int cur = ch & 1, nxt = 1 - cur;
        if (ch < 63) {
            cpG(ch + 1, nxt);
            ldgS(ch + 1);       // LDG latency hides under MMA below
        }
        mmaPhase(cur);
        if (ch < 63) {
            expStore(nxt);
            CP_WAIT0();
        }
        __syncthreads();
    }

    float* Yb = g_Yt + (size_t)b * CI * NB;
#pragma unroll
    for (int i = 0; i < 4; i++) {
        int c = wr * 64 + i * 16 + g;
#pragma unroll
        for (int j = 0; j < 4; j++) {
            int m = m0 + wc * 32 + j * 8 + 2 * tg;
            *(float2*)(Yb + (size_t)c * NB + m)       = make_float2(acc[i][j][0], acc[i][j][1]);
            *(float2*)(Yb + (size_t)(c + 8) * NB + m) = make_float2(acc[i][j][2], acc[i][j][3]);
        }
    }
}

// ---------------- K5a: WY[b,ct,n] = sum_ci w_w[ct,ci] * Yt[ci,n] + w_b[ct] ----
__global__ __launch_bounds__(256)
void wconv_kernel(const float* __restrict__ ww, const float* __restrict__ wb) {
    const int b   = blockIdx.z;
    const int ct0 = blockIdx.y * 128;
    const int n0  = blockIdx.x * 128;
    const int t   = threadIdx.x;
    const int tx  = t & 15, ty = t >> 4;
    __shared__ float As[8][128];
    __shared__ float Bs[8][128];
    float acc[8][8] = {};
    const float* Ytb = g_Yt + (size_t)b * CI * NB;

    for (int k0 = 0; k0 < CI; k0 += 8) {
        load_t(ww, ct0, CI, k0, As, t);
        load_d(Ytb, k0, NB, n0, Bs, t);
        __syncthreads();
        mma8x8(As, Bs, ty, tx, acc);
        __syncthreads();
    }

#pragma unroll
    for (int i = 0; i < 8; i++) {
        int   ct   = ct0 + ty * 8 + i;
        float bias = wb[ct];
        float4 r0 = make_float4(acc[i][0] + bias, acc[i][1] + bias,
                                acc[i][2] + bias, acc[i][3] + bias);
        float4 r1 = make_float4(acc[i][4] + bias, acc[i][5] + bias,
                                acc[i][6] + bias, acc[i][7] + bias);
        size_t row = ((size_t)(b * CT + ct)) * NB;
        *(float4*)(g_WY + row + n0 + tx * 8)     = r0;
        *(float4*)(g_WY + row + n0 + tx * 8 + 4) = r1;
    }
}

// ---------------- K5b: BN stats ----------------
__global__ __launch_bounds__(256)
void bnstats_kernel() {
    const int ct = blockIdx.x;
    const int t  = threadIdx.x;
    const int lane = t & 31, wrp = t >> 5;
    __shared__ float redS[8], redQ[8];

    float s = 0.f, q = 0.f;
    for (int b = 0; b < BQ; b++) {
        const float* p = g_WY + ((size_t)(b * CT + ct)) * NB;
        for (int i = t; i < NB; i += 256) {
            float v = p[i];
            s += v;
            q += v * v;
        }
    }
    s = warpSum(s);
    q = warpSum(q);
    if (lane == 0) { redS[wrp] = s; redQ[wrp] = q; }
    __syncthreads();
    if (wrp == 0) {
        float rs = (lane < 8) ? redS[lane] : 0.f;
        float rq = (lane < 8) ? redQ[lane] : 0.f;
        rs = warpSum(rs);
        rq = warpSum(rq);
        if (lane == 0) {
            const float invN = 1.f / (float)(BQ * NB);
            float mean = rs * invN;
            float var  = rq * invN - mean * mean;
            g_mean[ct] = mean;
            g_istd[ct] = rsqrtf(var + 1e-5f);
        }
    }
}

// ---------------- K5c: out = BN(WY)*gamma + beta + l ----------------
__global__ __launch_bounds__(256)
void finalize_kernel(const float* __restrict__ l, const float* __restrict__ gamma,
                     const float* __restrict__ beta, float* __restrict__ out) {
    const int ct = blockIdx.x;
    const int b  = blockIdx.y;
    const float sc  = g_istd[ct] * gamma[ct];
    const float off = beta[ct] - g_mean[ct] * sc;
    const size_t base = ((size_t)(b * CT + ct)) * NB;
    for (int i = threadIdx.x * 4; i < NB; i += 256 * 4) {
        float4 w  = *(const float4*)(g_WY + base + i);
        float4 lv = *(const float4*)(l + base + i);
        float4 o;
        o.x = fmaf(w.x, sc, off) + lv.x;
        o.y = fmaf(w.y, sc, off) + lv.y;
        o.z = fmaf(w.z, sc, off) + lv.z;
        o.w = fmaf(w.w, sc, off) + lv.w;
        *(float4*)(out + base + i) = o;
    }
}

// ---------------- launch ----------------
extern "C" void kernel_launch(void* const* d_in, const int* in_sizes, int n_in,
                              void* d_out, int out_size) {
    const float* x     = (const float*)d_in[0];
    const float* l     = (const float*)d_in[1];
    const float* gw    = (const float*)d_in[2];
    const float* gb    = (const float*)d_in[3];
    const float* thw   = (const float*)d_in[4];
    const float* thb   = (const float*)d_in[5];
    const float* phw   = (const float*)d_in[6];
    const float* phb   = (const float*)d_in[7];
    const float* ww    = (const float*)d_in[8];
    const float* wb    = (const float*)d_in[9];
    const float* gamma = (const float*)d_in[10];
    const float* beta  = (const float*)d_in[11];
    float* out = (float*)d_out;

    static int smem_set = 0;
    if (!smem_set) {
        cudaFuncSetAttribute(qk_mma_kernel, cudaFuncAttributeMaxDynamicSharedMemorySize, 4 * QK_TILE);
        cudaFuncSetAttribute(av_mma_kernel, cudaFuncAttributeMaxDynamicSharedMemorySize, 2 * AV_BUF);
        smem_set = 1;
    }

    dim3 thr(256);
    proj_kernel<<<dim3(32, BQ), thr>>>(x, thw, thb, 0);   // TH
    proj_kernel<<<dim3(32, BQ), thr>>>(x, gw,  gb,  1);   // G (transposed)
    proj_kernel<<<dim3(32, BQ), thr>>>(l, phw, phb, 2);   // PH
    qk_mma_kernel<<<dim3(32, 32, BQ), thr, 4 * QK_TILE>>>();
    rowstats_kernel<<<dim3(NB, BQ), thr>>>();
    av_mma_kernel<<<dim3(32, BQ), thr, 2 * AV_BUF>>>();
    wconv_kernel<<<dim3(32, 2, BQ), thr>>>(ww, wb);
    bnstats_kernel<<<dim3(CT), thr>>>();
    finalize_kernel<<<dim3(CT, BQ), thr>>>(l, gamma, beta, out);
}